// round 14
// baseline (speedup 1.0000x reference)
#include <cuda_runtime.h>
#include <cuda_fp16.h>
#include <cstdint>

#define Bsz 4
#define Sq  2048
#define Emb 768
#define NH  12
#define HD  64
#define NT  (Sq / 64)            // 32 k-tiles of 64 keys
#define L2E 1.4426950408889634f

// Q, K: [B,H,S,D] half, D pair-interleaved within 16-groups.
// V: [B,H,D,S] half, S pair-interleaved within 16-groups.
// Q pre-scaled by 0.125 * log2(e).
__device__ __half g_Q[(size_t)Bsz * NH * Sq * HD];
__device__ __half g_K[(size_t)Bsz * NH * Sq * HD];
__device__ __half g_V[(size_t)Bsz * NH * Sq * HD];

// ---------------------------------------------------------------------------
// helpers
// ---------------------------------------------------------------------------
__device__ __forceinline__ unsigned h2pk(float lo, float hi) {
    unsigned r;
    asm("cvt.rn.f16x2.f32 %0, %1, %2;" : "=r"(r) : "f"(hi), "f"(lo));
    return r;
}
__device__ __forceinline__ float ex2f(float x) {
    float r;
    asm("ex2.approx.f32 %0, %1;" : "=f"(r) : "f"(x));
    return r;
}
__device__ __forceinline__ void mma_f16(float* d, const unsigned* a, const unsigned* b) {
    asm volatile(
        "mma.sync.aligned.m16n8k16.row.col.f32.f16.f16.f32 "
        "{%0,%1,%2,%3}, {%4,%5,%6,%7}, {%8,%9}, {%0,%1,%2,%3};"
        : "+f"(d[0]), "+f"(d[1]), "+f"(d[2]), "+f"(d[3])
        : "r"(a[0]), "r"(a[1]), "r"(a[2]), "r"(a[3]), "r"(b[0]), "r"(b[1]));
}
__device__ __forceinline__ void cpa16(void* s, const void* g) {
    unsigned sa = (unsigned)__cvta_generic_to_shared(s);
    asm volatile("cp.async.cg.shared.global [%0], [%1], 16;" :: "r"(sa), "l"(g));
}
#define CP_COMMIT()  asm volatile("cp.async.commit_group;")
#define CP_WAIT(N)   asm volatile("cp.async.wait_group %0;" :: "n"(N))

// ---------------------------------------------------------------------------
// Kernel 1: fused QKV projection, fp16 mma (fp32 accum). (Proven version.)
// ---------------------------------------------------------------------------
#define XW 24

__global__ __launch_bounds__(256, 2)
void qkv_kernel(const float* __restrict__ X,
                const float* __restrict__ Wq, const float* __restrict__ bq,
                const float* __restrict__ Wk, const float* __restrict__ bk,
                const float* __restrict__ Wv, const float* __restrict__ bv)
{
    __shared__ uint32_t Xs[128][XW];
    __shared__ uint32_t Ws[128][XW];

    const int tid = threadIdx.x;
    const int w   = tid >> 5;
    const int l   = tid & 31;
    const int wm  = w >> 1;
    const int wn  = w & 1;
    const int lg  = l >> 2;
    const int lt  = l & 3;

    const int bx    = blockIdx.x;
    const int row0  = blockIdx.y * 128;
    const int which = bx / 6;
    const int o0    = (bx % 6) * 128;

    const float* W    = (which == 0) ? Wq : (which == 1) ? Wk : Wv;
    const float* bias = (which == 0) ? bq : (which == 1) ? bk : bv;
    __half*      dst  = (which == 0) ? g_Q : (which == 1) ? g_K : g_V;
    const float scale = (which == 0) ? (0.125f * L2E) : 1.0f;

    float acc[2][8][4];
    #pragma unroll
    for (int mt = 0; mt < 2; mt++)
        #pragma unroll
        for (int nt = 0; nt < 8; nt++)
            #pragma unroll
            for (int j = 0; j < 4; j++) acc[mt][nt][j] = 0.f;

    const int cr = tid >> 1;
    const int cg = tid & 1;

    for (int kt = 0; kt < Emb / 32; kt++) {
        const int k0 = kt * 32 + cg * 16;
        {
            float4 u0 = *(const float4*)&X[(size_t)(row0 + cr) * Emb + k0 + 0];
            float4 u1 = *(const float4*)&X[(size_t)(row0 + cr) * Emb + k0 + 4];
            float4 u2 = *(const float4*)&X[(size_t)(row0 + cr) * Emb + k0 + 8];
            float4 u3 = *(const float4*)&X[(size_t)(row0 + cr) * Emb + k0 + 12];
            uint4 s1 = make_uint4(h2pk(u0.x,u0.y), h2pk(u2.x,u2.y),
                                  h2pk(u0.z,u0.w), h2pk(u2.z,u2.w));
            uint4 s2 = make_uint4(h2pk(u1.x,u1.y), h2pk(u3.x,u3.y),
                                  h2pk(u1.z,u1.w), h2pk(u3.z,u3.w));
            *(uint4*)&Xs[cr][cg * 8 + 0] = s1;
            *(uint4*)&Xs[cr][cg * 8 + 4] = s2;
            u0 = *(const float4*)&W[(size_t)(o0 + cr) * Emb + k0 + 0];
            u1 = *(const float4*)&W[(size_t)(o0 + cr) * Emb + k0 + 4];
            u2 = *(const float4*)&W[(size_t)(o0 + cr) * Emb + k0 + 8];
            u3 = *(const float4*)&W[(size_t)(o0 + cr) * Emb + k0 + 12];
            s1 = make_uint4(h2pk(u0.x,u0.y), h2pk(u2.x,u2.y),
                            h2pk(u0.z,u0.w), h2pk(u2.z,u2.w));
            s2 = make_uint4(h2pk(u1.x,u1.y), h2pk(u3.x,u3.y),
                            h2pk(u1.z,u1.w), h2pk(u3.z,u3.w));
            *(uint4*)&Ws[cr][cg * 8 + 0] = s1;
            *(uint4*)&Ws[cr][cg * 8 + 4] = s2;
        }
        __syncthreads();

        #pragma unroll
        for (int g = 0; g < 2; g++) {
            unsigned a[2][4];
            #pragma unroll
            for (int mt = 0; mt < 2; mt++) {
                const int rb = 32 * wm + 16 * mt + lg;
                uint2 lo = *(const uint2*)&Xs[rb    ][8 * g + 2 * lt];
                uint2 hi = *(const uint2*)&Xs[rb + 8][8 * g + 2 * lt];
                a[mt][0] = lo.x; a[mt][1] = hi.x; a[mt][2] = lo.y; a[mt][3] = hi.y;
            }
            #pragma unroll
            for (int nt = 0; nt < 8; nt++) {
                const int br = 64 * wn + 8 * nt + lg;
                uint2 bb = *(const uint2*)&Ws[br][8 * g + 2 * lt];
                mma_f16(acc[0][nt], a[0], (const unsigned*)&bb);
                mma_f16(acc[1][nt], a[1], (const unsigned*)&bb);
            }
        }
        __syncthreads();
    }

    const int bb_ = row0 >> 11;
    const int sb  = row0 & 2047;

    if (which < 2) {
        #pragma unroll
        for (int nt = 0; nt < 8; nt++) {
            const int ob = o0 + 64 * wn + 8 * nt;
            const int h  = ob >> 6;
            const int dphys = (nt >> 1) * 16 + 4 * lt + 2 * (nt & 1);
            float2 bv2 = *(const float2*)&bias[ob + 2 * lt];
            __half* base = dst + (((size_t)bb_ * NH + h) * Sq) * HD;
            #pragma unroll
            for (int mt = 0; mt < 2; mt++) {
                #pragma unroll
                for (int i = 0; i < 2; i++) {
                    const int s = sb + 32 * wm + 16 * mt + lg + 8 * i;
                    const float v0 = (acc[mt][nt][2 * i    ] + bv2.x) * scale;
                    const float v1 = (acc[mt][nt][2 * i + 1] + bv2.y) * scale;
                    *(uint32_t*)&base[(size_t)s * HD + dphys] = h2pk(v0, v1);
                }
            }
        }
    } else {
        #pragma unroll
        for (int nt = 0; nt < 8; nt++) {
            const int ob = o0 + 64 * wn + 8 * nt;
            const int h  = ob >> 6;
            const int d0 = 8 * nt + 2 * lt;
            float2 bv2 = *(const float2*)&bias[ob + 2 * lt];
            __half* base = dst + (((size_t)bb_ * NH + h) * HD) * Sq;
            #pragma unroll
            for (int mt = 0; mt < 2; mt++) {
                #pragma unroll
                for (int i = 0; i < 2; i++) {
                    const int sgrp  = sb + 32 * wm + 16 * mt;
                    const int sphys = sgrp + 4 * (lg >> 1) + 2 * i + (lg & 1);
                    base[(size_t)(d0    ) * Sq + sphys] =
                        __float2half_rn(acc[mt][nt][2 * i    ] + bv2.x);
                    base[(size_t)(d0 + 1) * Sq + sphys] =
                        __float2half_rn(acc[mt][nt][2 * i + 1] + bv2.y);
                }
            }
        }
    }
}

// ---------------------------------------------------------------------------
// Kernel 2: fp16 flash attention, m32 warp tiles, 32-key half-passes.
// dm mask staged in smem via cp.async (1 tile ahead) — no register staging.
// 128 thr/CTA, 2 CTAs/SM, KROW=160, DMROW=288 (both conflict-free).
// ---------------------------------------------------------------------------
#define KROW 160
#define KTB  (64 * KROW)          // 10240
#define DMROW 288                 // 64 floats + 32B pad (72 words = 8 mod 32)
#define DMB   (128 * DMROW)       // 36864
#define ATTN_SMEM (4 * KTB + DMB) // 77824

__global__ __launch_bounds__(128, 2)
void attn_kernel(const float* __restrict__ am,   // [B,1,1,S]
                 const float* __restrict__ dm,   // [B,1,S,S]
                 float* __restrict__ out)        // [B,S,E]
{
    extern __shared__ char smc[];
    char* Kb[2] = { smc,           smc + KTB     };
    char* Vb[2] = { smc + 2 * KTB, smc + 3 * KTB };
    char* Dm    = smc + 4 * KTB;

    const int tid = threadIdx.x;
    const int w   = tid >> 5;
    const int l   = tid & 31;
    const int lg  = l >> 2;
    const int lt  = l & 3;

    const int q0 = blockIdx.x * 128;
    const int h  = blockIdx.y;
    const int b  = blockIdx.z;

    const char* Kg = (const char*)(g_K + ((size_t)b * NH + h) * Sq * HD);
    const char* Vg = (const char*)(g_V + ((size_t)b * NH + h) * HD * Sq);
    const __half* Qg = g_Q + ((size_t)b * NH + h) * Sq * HD;
    const float* amb = am + (size_t)b * Sq;
    const float* dmb = dm + ((size_t)b * Sq + q0) * Sq;

    const int qr = q0 + 32 * w + lg;   // rows handled: qr, +8, +16, +24

    // dm cp.async mapping: 16 chunks per thread covers 128 rows x 256B
    const int dr = tid >> 4;           // base row group: thread covers rows dr + 8*i? no:
    // c = tid + 128*i  ->  r = c>>4 (0..127), j = c&15
    // (computed inline below)

    // Q fragments: 4 k16-groups x 8 regs (0-3: rows +0/+8; 4-7: rows +16/+24)
    unsigned qa[4][8];
    #pragma unroll
    for (int ks = 0; ks < 4; ks++) {
        uint2 u0 = *(const uint2*)((const char*)Qg + ((size_t)(qr     ) * HD + ks * 16) * 2 + 8 * lt);
        uint2 u1 = *(const uint2*)((const char*)Qg + ((size_t)(qr +  8) * HD + ks * 16) * 2 + 8 * lt);
        uint2 u2 = *(const uint2*)((const char*)Qg + ((size_t)(qr + 16) * HD + ks * 16) * 2 + 8 * lt);
        uint2 u3 = *(const uint2*)((const char*)Qg + ((size_t)(qr + 24) * HD + ks * 16) * 2 + 8 * lt);
        qa[ks][0] = u0.x; qa[ks][1] = u1.x; qa[ks][2] = u0.y; qa[ks][3] = u1.y;
        qa[ks][4] = u2.x; qa[ks][5] = u3.x; qa[ks][6] = u2.y; qa[ks][7] = u3.y;
    }
    (void)dr;

    float o[8][8];
    #pragma unroll
    for (int nt = 0; nt < 8; nt++)
        #pragma unroll
        for (int j = 0; j < 8; j++) o[nt][j] = 0.f;
    float lr[4] = {0.f, 0.f, 0.f, 0.f};

    // prologue: K/V tile 0 + dm tile 0
    #pragma unroll
    for (int i = 0; i < 4; i++) {
        const int c = tid + 128 * i;
        const int r = c >> 3, j = c & 7;
        cpa16(Kb[0] + r * KROW + j * 16, Kg + (size_t)r * 128 + j * 16);
        cpa16(Vb[0] + r * KROW + j * 16, Vg + (size_t)r * 4096 + j * 16);
    }
    #pragma unroll
    for (int i = 0; i < 16; i++) {
        const int c = tid + 128 * i;
        const int r = c >> 4, j = c & 15;
        cpa16(Dm + r * DMROW + j * 16, &dmb[(size_t)r * Sq + 4 * j]);
    }
    CP_COMMIT();

    for (int t = 0; t < NT; t++) {
        const int k0 = t * 64;
        const char* Kc = Kb[t & 1];
        const char* Vc = Vb[t & 1];

        CP_WAIT(0);            // K/V[t] and dm[t] resident
        __syncthreads();

        // prefetch K/V tile t+1 (wraps harmlessly)
        {
            const int kn = (t + 1 < NT) ? (k0 + 64) : 0;
            char* Kn = Kb[(t + 1) & 1];
            char* Vn = Vb[(t + 1) & 1];
            #pragma unroll
            for (int i = 0; i < 4; i++) {
                const int c = tid + 128 * i;
                const int r = c >> 3, j = c & 7;
                cpa16(Kn + r * KROW + j * 16, Kg + (size_t)(kn + r) * 128 + j * 16);
                cpa16(Vn + r * KROW + j * 16, Vg + (size_t)r * 4096 + kn * 2 + j * 16);
            }
            CP_COMMIT();
        }

        // two 32-key half-passes
        #pragma unroll
        for (int kh = 0; kh < 2; kh++) {
            const int kc = k0 + 32 * kh + 2 * lt;   // global key pair base (for am)
            const int kw = 32 * kh + 2 * lt;        // within-tile key word base (for Dm)

            // S = Q K^T for keys [32kh, 32kh+32)
            float s[4][8];
            #pragma unroll
            for (int nt = 0; nt < 4; nt++)
                #pragma unroll
                for (int j = 0; j < 8; j++) s[nt][j] = 0.f;

            #pragma unroll
            for (int ks = 0; ks < 4; ks++) {
                #pragma unroll
                for (int nt = 0; nt < 4; nt++) {
                    uint2 kb = *(const uint2*)(Kc + (32 * kh + 8 * nt + lg) * KROW + ks * 32 + 8 * lt);
                    mma_f16(&s[nt][0], &qa[ks][0], (const unsigned*)&kb);
                    mma_f16(&s[nt][4], &qa[ks][4], (const unsigned*)&kb);
                }
            }

            // masks (am LDG / dm LDS) + fp32 exp + row sums; pack P a-frags
            unsigned pa[2][2][4];
            #pragma unroll
            for (int h2 = 0; h2 < 2; h2++) {
                const int ra = 32 * w + 16 * h2 + lg;
                #pragma unroll
                for (int nt = 0; nt < 4; nt++) {
                    const float2 amv = *(const float2*)&amb[kc + 8 * nt];
                    const float2 d0 = *(const float2*)(Dm + (ra    ) * DMROW + (kw + 8 * nt) * 4);
                    const float2 d1 = *(const float2*)(Dm + (ra + 8) * DMROW + (kw + 8 * nt) * 4);
                    const float p00 = ex2f(fmaf(d0.x, L2E, fmaf(amv.x, L2E, s[nt][4*h2+0])));
                    const float p01 = ex2f(fmaf(d0.y, L2E, fmaf(amv.y, L2E, s[nt][4*h2+1])));
                    const float p10 = ex2f(fmaf(d1.x, L2E, fmaf(amv.x, L2E, s[nt][4*h2+2])));
                    const float p11 = ex2f(fmaf(d1.y, L2E, fmaf(amv.y, L2E, s[nt][4*h2+3])));
                    lr[2*h2    ] += p00 + p01;
                    lr[2*h2 + 1] += p10 + p11;
                    pa[h2][nt >> 1][(nt & 1) * 2 + 0] = h2pk(p00, p01);
                    pa[h2][nt >> 1][(nt & 1) * 2 + 1] = h2pk(p10, p11);
                }
            }

            // O += P V for this key half
            #pragma unroll
            for (int ks2 = 0; ks2 < 2; ks2++) {
                const int kso = (2 * kh + ks2) * 32;
                #pragma unroll
                for (int nt = 0; nt < 8; nt++) {
                    uint2 vb = *(const uint2*)(Vc + (8 * nt + lg) * KROW + kso + 8 * lt);
                    mma_f16(&o[nt][0], pa[0][ks2], (const unsigned*)&vb);
                    mma_f16(&o[nt][4], pa[1][ks2], (const unsigned*)&vb);
                }
            }
        }

        // dm[t] fully consumed; stage dm[t+1]
        __syncthreads();
        if (t + 1 < NT) {
            const int kn = k0 + 64;
            #pragma unroll
            for (int i = 0; i < 16; i++) {
                const int c = tid + 128 * i;
                const int r = c >> 4, j = c & 15;
                cpa16(Dm + r * DMROW + j * 16, &dmb[(size_t)r * Sq + kn + 4 * j]);
            }
            CP_COMMIT();
        }
    }

    // row-sum reduce across the 4 lt lanes, normalize, write out
    #pragma unroll
    for (int i = 0; i < 4; i++) {
        lr[i] += __shfl_xor_sync(0xffffffffu, lr[i], 1);
        lr[i] += __shfl_xor_sync(0xffffffffu, lr[i], 2);
    }
    const float inv0 = 1.0f / lr[0];
    const float inv1 = 1.0f / lr[1];
    const float inv2 = 1.0f / lr[2];
    const float inv3 = 1.0f / lr[3];

    #pragma unroll
    for (int nt = 0; nt < 8; nt++) {
        const int col = h * HD + 8 * nt + 2 * lt;
        float2 r;
        r.x = o[nt][0] * inv0; r.y = o[nt][1] * inv0;
        *(float2*)&out[((size_t)b * Sq + qr     ) * Emb + col] = r;
        r.x = o[nt][2] * inv1; r.y = o[nt][3] * inv1;
        *(float2*)&out[((size_t)b * Sq + qr +  8) * Emb + col] = r;
        r.x = o[nt][4] * inv2; r.y = o[nt][5] * inv2;
        *(float2*)&out[((size_t)b * Sq + qr + 16) * Emb + col] = r;
        r.x = o[nt][6] * inv3; r.y = o[nt][7] * inv3;
        *(float2*)&out[((size_t)b * Sq + qr + 24) * Emb + col] = r;
    }
}

// ---------------------------------------------------------------------------
extern "C" void kernel_launch(void* const* d_in, const int* in_sizes, int n_in,
                              void* d_out, int out_size)
{
    const float* X  = (const float*)d_in[0];
    const float* am = (const float*)d_in[1];
    const float* dm = (const float*)d_in[2];
    const float* Wq = (const float*)d_in[3];
    const float* bq = (const float*)d_in[4];
    const float* Wk = (const float*)d_in[5];
    const float* bk = (const float*)d_in[6];
    const float* Wv = (const float*)d_in[7];
    const float* bv = (const float*)d_in[8];
    float* out = (float*)d_out;

    qkv_kernel<<<dim3(18, 64), 256>>>(X, Wq, bq, Wk, bk, Wv, bv);

    cudaFuncSetAttribute(attn_kernel,
                         cudaFuncAttributeMaxDynamicSharedMemorySize,
                         ATTN_SMEM);
    attn_kernel<<<dim3(Sq / 128, NH, Bsz), 128, ATTN_SMEM>>>(am, dm, out);
}

// round 15
// speedup vs baseline: 1.1897x; 1.1897x over previous
#include <cuda_runtime.h>
#include <cuda_fp16.h>
#include <cstdint>

#define Bsz 4
#define Sq  2048
#define Emb 768
#define NH  12
#define HD  64
#define NT  (Sq / 64)            // 32 k-tiles of 64 keys
#define L2E 1.4426950408889634f

// Q, K: [B,H,S,D] half, D pair-interleaved within 16-groups.
// V: [B,H,D,S] half, S pair-interleaved within 16-groups.
// Q pre-scaled by 0.125 * log2(e).
__device__ __half g_Q[(size_t)Bsz * NH * Sq * HD];
__device__ __half g_K[(size_t)Bsz * NH * Sq * HD];
__device__ __half g_V[(size_t)Bsz * NH * Sq * HD];

// fp16 pre-converted inputs (k pair-interleaved within 16-groups), as words
#define XROWS (Bsz * Sq)         // 8192
#define WROWS (3 * Emb)          // 2304
__device__ uint32_t g_X16[(size_t)XROWS * (Emb / 2)];   // 12.6 MB
__device__ uint32_t g_W16[(size_t)WROWS * (Emb / 2)];   // 3.5 MB

// ---------------------------------------------------------------------------
// helpers
// ---------------------------------------------------------------------------
__device__ __forceinline__ unsigned h2pk(float lo, float hi) {
    unsigned r;
    asm("cvt.rn.f16x2.f32 %0, %1, %2;" : "=r"(r) : "f"(hi), "f"(lo));
    return r;
}
__device__ __forceinline__ float ex2f(float x) {
    float r;
    asm("ex2.approx.f32 %0, %1;" : "=f"(r) : "f"(x));
    return r;
}
__device__ __forceinline__ void mma_f16(float* d, const unsigned* a, const unsigned* b) {
    asm volatile(
        "mma.sync.aligned.m16n8k16.row.col.f32.f16.f16.f32 "
        "{%0,%1,%2,%3}, {%4,%5,%6,%7}, {%8,%9}, {%0,%1,%2,%3};"
        : "+f"(d[0]), "+f"(d[1]), "+f"(d[2]), "+f"(d[3])
        : "r"(a[0]), "r"(a[1]), "r"(a[2]), "r"(a[3]), "r"(b[0]), "r"(b[1]));
}
__device__ __forceinline__ void cpa16(void* s, const void* g) {
    unsigned sa = (unsigned)__cvta_generic_to_shared(s);
    asm volatile("cp.async.cg.shared.global [%0], [%1], 16;" :: "r"(sa), "l"(g));
}
#define CP_COMMIT()  asm volatile("cp.async.commit_group;")
#define CP_WAIT(N)   asm volatile("cp.async.wait_group %0;" :: "n"(N))

// ---------------------------------------------------------------------------
// Kernel 0: convert X / Wq / Wk / Wv to fp16 words, pair-interleaved per
// 16-k group: words = (k0k1)(k8k9)(k2k3)(k10k11)(k4k5)(k12k13)(k6k7)(k14k15)
// ---------------------------------------------------------------------------
#define NGRP (Emb / 16)          // 48
#define CVT_TOT ((XROWS + WROWS) * NGRP)

__global__ __launch_bounds__(256)
void precvt_kernel(const float* __restrict__ X,
                   const float* __restrict__ Wq,
                   const float* __restrict__ Wk,
                   const float* __restrict__ Wv)
{
    const int g = blockIdx.x * 256 + threadIdx.x;
    if (g >= CVT_TOT) return;
    const int row = g / NGRP;
    const int grp = g % NGRP;

    const float* src;
    uint32_t*    dst;
    if (row < XROWS) {
        src = X + (size_t)row * Emb;
        dst = g_X16 + (size_t)row * (Emb / 2);
    } else {
        const int wr = row - XROWS;
        const float* Wm = (wr < Emb) ? Wq : (wr < 2 * Emb) ? Wk : Wv;
        const int wi = (wr < Emb) ? wr : (wr < 2 * Emb) ? wr - Emb : wr - 2 * Emb;
        src = Wm + (size_t)wi * Emb;
        dst = g_W16 + (size_t)wr * (Emb / 2);
    }

    const float4 u0 = *(const float4*)(src + grp * 16 + 0);
    const float4 u1 = *(const float4*)(src + grp * 16 + 4);
    const float4 u2 = *(const float4*)(src + grp * 16 + 8);
    const float4 u3 = *(const float4*)(src + grp * 16 + 12);
    uint4 s1 = make_uint4(h2pk(u0.x,u0.y), h2pk(u2.x,u2.y),
                          h2pk(u0.z,u0.w), h2pk(u2.z,u2.w));
    uint4 s2 = make_uint4(h2pk(u1.x,u1.y), h2pk(u3.x,u3.y),
                          h2pk(u1.z,u1.w), h2pk(u3.z,u3.w));
    *(uint4*)(dst + grp * 8 + 0) = s1;
    *(uint4*)(dst + grp * 8 + 4) = s2;
}

// ---------------------------------------------------------------------------
// Kernel 1: fused QKV projection, fp16 mma, cp.async double-buffered.
// Grid x=18 (6 n-tiles per matrix), y=64 token tiles of 128.
// Block 256 = 8 warps as 4(m) x 2(n); warp tile 32m x 64n; k-tile 32.
// smem row stride 24 words (96B) — proven conflict-free for frag LDS.64.
// ---------------------------------------------------------------------------
#define QW 24

__global__ __launch_bounds__(256, 2)
void qkv_kernel(const float* __restrict__ bq,
                const float* __restrict__ bk,
                const float* __restrict__ bv)
{
    __shared__ uint32_t Xs[2][128][QW];
    __shared__ uint32_t Ws[2][128][QW];

    const int tid = threadIdx.x;
    const int w   = tid >> 5;
    const int l   = tid & 31;
    const int wm  = w >> 1;
    const int wn  = w & 1;
    const int lg  = l >> 2;
    const int lt  = l & 3;

    const int bx    = blockIdx.x;
    const int row0  = blockIdx.y * 128;
    const int which = bx / 6;
    const int o0    = (bx % 6) * 128;

    const float* bias = (which == 0) ? bq : (which == 1) ? bk : bv;
    __half*      dst  = (which == 0) ? g_Q : (which == 1) ? g_K : g_V;
    const float scale = (which == 0) ? (0.125f * L2E) : 1.0f;

    const uint32_t* Xg = g_X16 + (size_t)row0 * (Emb / 2);
    const uint32_t* Wg = g_W16 + ((size_t)which * Emb + o0) * (Emb / 2);

    float acc[2][8][4];
    #pragma unroll
    for (int mt = 0; mt < 2; mt++)
        #pragma unroll
        for (int nt = 0; nt < 8; nt++)
            #pragma unroll
            for (int j = 0; j < 4; j++) acc[mt][nt][j] = 0.f;

    // cp.async mapping: 512 chunks per tensor per tile; thread does 2 each
    const int c0 = tid, c1 = tid + 256;
    const int r0 = c0 >> 2, j0 = c0 & 3;
    const int r1 = c1 >> 2, j1 = c1 & 3;

    // prologue: tile 0
    cpa16(&Xs[0][r0][j0 * 4], Xg + (size_t)r0 * 384 + j0 * 4);
    cpa16(&Xs[0][r1][j1 * 4], Xg + (size_t)r1 * 384 + j1 * 4);
    cpa16(&Ws[0][r0][j0 * 4], Wg + (size_t)r0 * 384 + j0 * 4);
    cpa16(&Ws[0][r1][j1 * 4], Wg + (size_t)r1 * 384 + j1 * 4);
    CP_COMMIT();

    for (int kt = 0; kt < Emb / 32; kt++) {
        const int cur = kt & 1, nxt = cur ^ 1;

        CP_WAIT(0);
        __syncthreads();

        // prefetch tile kt+1 (wraps harmlessly on last iter)
        {
            const int kn = (kt + 1 < Emb / 32) ? (kt + 1) * 16 : 0;
            cpa16(&Xs[nxt][r0][j0 * 4], Xg + (size_t)r0 * 384 + kn + j0 * 4);
            cpa16(&Xs[nxt][r1][j1 * 4], Xg + (size_t)r1 * 384 + kn + j1 * 4);
            cpa16(&Ws[nxt][r0][j0 * 4], Wg + (size_t)r0 * 384 + kn + j0 * 4);
            cpa16(&Ws[nxt][r1][j1 * 4], Wg + (size_t)r1 * 384 + kn + j1 * 4);
            CP_COMMIT();
        }

        #pragma unroll
        for (int g = 0; g < 2; g++) {
            unsigned a[2][4];
            #pragma unroll
            for (int mt = 0; mt < 2; mt++) {
                const int rb = 32 * wm + 16 * mt + lg;
                uint2 lo = *(const uint2*)&Xs[cur][rb    ][8 * g + 2 * lt];
                uint2 hi = *(const uint2*)&Xs[cur][rb + 8][8 * g + 2 * lt];
                a[mt][0] = lo.x; a[mt][1] = hi.x; a[mt][2] = lo.y; a[mt][3] = hi.y;
            }
            #pragma unroll
            for (int nt = 0; nt < 8; nt++) {
                const int br = 64 * wn + 8 * nt + lg;
                uint2 bb = *(const uint2*)&Ws[cur][br][8 * g + 2 * lt];
                mma_f16(acc[0][nt], a[0], (const unsigned*)&bb);
                mma_f16(acc[1][nt], a[1], (const unsigned*)&bb);
            }
        }
        __syncthreads();
    }

    const int bb_ = row0 >> 11;
    const int sb  = row0 & 2047;

    if (which < 2) {
        #pragma unroll
        for (int nt = 0; nt < 8; nt++) {
            const int ob = o0 + 64 * wn + 8 * nt;
            const int h  = ob >> 6;
            const int dphys = (nt >> 1) * 16 + 4 * lt + 2 * (nt & 1);
            float2 bv2 = *(const float2*)&bias[ob + 2 * lt];
            __half* base = dst + (((size_t)bb_ * NH + h) * Sq) * HD;
            #pragma unroll
            for (int mt = 0; mt < 2; mt++) {
                #pragma unroll
                for (int i = 0; i < 2; i++) {
                    const int s = sb + 32 * wm + 16 * mt + lg + 8 * i;
                    const float v0 = (acc[mt][nt][2 * i    ] + bv2.x) * scale;
                    const float v1 = (acc[mt][nt][2 * i + 1] + bv2.y) * scale;
                    *(uint32_t*)&base[(size_t)s * HD + dphys] = h2pk(v0, v1);
                }
            }
        }
    } else {
        #pragma unroll
        for (int nt = 0; nt < 8; nt++) {
            const int ob = o0 + 64 * wn + 8 * nt;
            const int h  = ob >> 6;
            const int d0 = 8 * nt + 2 * lt;
            float2 bv2 = *(const float2*)&bias[ob + 2 * lt];
            __half* base = dst + (((size_t)bb_ * NH + h) * HD) * Sq;
            #pragma unroll
            for (int mt = 0; mt < 2; mt++) {
                #pragma unroll
                for (int i = 0; i < 2; i++) {
                    const int sgrp  = sb + 32 * wm + 16 * mt;
                    const int sphys = sgrp + 4 * (lg >> 1) + 2 * i + (lg & 1);
                    base[(size_t)(d0    ) * Sq + sphys] =
                        __float2half_rn(acc[mt][nt][2 * i    ] + bv2.x);
                    base[(size_t)(d0 + 1) * Sq + sphys] =
                        __float2half_rn(acc[mt][nt][2 * i + 1] + bv2.y);
                }
            }
        }
    }
}

// ---------------------------------------------------------------------------
// Kernel 2: fp16 flash attention, m32 warp tiles, 32-key half-passes.
// dm staged in smem; 128 thr/CTA, *3 CTAs/SM* (regs capped), KROW=160.
// ---------------------------------------------------------------------------
#define KROW 160
#define KTB  (64 * KROW)          // 10240
#define DMROW 272                 // 64 floats + 16B pad
#define DMB   (128 * DMROW)       // 34816
#define ATTN_SMEM (4 * KTB + DMB) // 75776  -> 3 CTAs/SM

__global__ __launch_bounds__(128, 3)
void attn_kernel(const float* __restrict__ am,   // [B,1,1,S]
                 const float* __restrict__ dm,   // [B,1,S,S]
                 float* __restrict__ out)        // [B,S,E]
{
    extern __shared__ char smc[];
    char* Kb[2] = { smc,           smc + KTB     };
    char* Vb[2] = { smc + 2 * KTB, smc + 3 * KTB };
    char* Dm    = smc + 4 * KTB;

    const int tid = threadIdx.x;
    const int w   = tid >> 5;
    const int l   = tid & 31;
    const int lg  = l >> 2;
    const int lt  = l & 3;

    const int q0 = blockIdx.x * 128;
    const int h  = blockIdx.y;
    const int b  = blockIdx.z;

    const char* Kg = (const char*)(g_K + ((size_t)b * NH + h) * Sq * HD);
    const char* Vg = (const char*)(g_V + ((size_t)b * NH + h) * HD * Sq);
    const __half* Qg = g_Q + ((size_t)b * NH + h) * Sq * HD;
    const float* amb = am + (size_t)b * Sq;
    const float* dmb = dm + ((size_t)b * Sq + q0) * Sq;

    const int qr = q0 + 32 * w + lg;   // rows handled: qr, +8, +16, +24

    // Q fragments: 4 k16-groups x 8 regs (0-3: rows +0/+8; 4-7: rows +16/+24)
    unsigned qa[4][8];
    #pragma unroll
    for (int ks = 0; ks < 4; ks++) {
        uint2 u0 = *(const uint2*)((const char*)Qg + ((size_t)(qr     ) * HD + ks * 16) * 2 + 8 * lt);
        uint2 u1 = *(const uint2*)((const char*)Qg + ((size_t)(qr +  8) * HD + ks * 16) * 2 + 8 * lt);
        uint2 u2 = *(const uint2*)((const char*)Qg + ((size_t)(qr + 16) * HD + ks * 16) * 2 + 8 * lt);
        uint2 u3 = *(const uint2*)((const char*)Qg + ((size_t)(qr + 24) * HD + ks * 16) * 2 + 8 * lt);
        qa[ks][0] = u0.x; qa[ks][1] = u1.x; qa[ks][2] = u0.y; qa[ks][3] = u1.y;
        qa[ks][4] = u2.x; qa[ks][5] = u3.x; qa[ks][6] = u2.y; qa[ks][7] = u3.y;
    }

    float o[8][8];
    #pragma unroll
    for (int nt = 0; nt < 8; nt++)
        #pragma unroll
        for (int j = 0; j < 8; j++) o[nt][j] = 0.f;
    float lr[4] = {0.f, 0.f, 0.f, 0.f};

    // prologue: K/V tile 0 + dm tile 0
    #pragma unroll
    for (int i = 0; i < 4; i++) {
        const int c = tid + 128 * i;
        const int r = c >> 3, j = c & 7;
        cpa16(Kb[0] + r * KROW + j * 16, Kg + (size_t)r * 128 + j * 16);
        cpa16(Vb[0] + r * KROW + j * 16, Vg + (size_t)r * 4096 + j * 16);
    }
    #pragma unroll
    for (int i = 0; i < 16; i++) {
        const int c = tid + 128 * i;
        const int r = c >> 4, j = c & 15;
        cpa16(Dm + r * DMROW + j * 16, &dmb[(size_t)r * Sq + 4 * j]);
    }
    CP_COMMIT();

    for (int t = 0; t < NT; t++) {
        const int k0 = t * 64;
        const char* Kc = Kb[t & 1];
        const char* Vc = Vb[t & 1];

        CP_WAIT(0);            // K/V[t] and dm[t] resident
        __syncthreads();

        // prefetch K/V tile t+1 (wraps harmlessly)
        {
            const int kn = (t + 1 < NT) ? (k0 + 64) : 0;
            char* Kn = Kb[(t + 1) & 1];
            char* Vn = Vb[(t + 1) & 1];
            #pragma unroll
            for (int i = 0; i < 4; i++) {
                const int c = tid + 128 * i;
                const int r = c >> 3, j = c & 7;
                cpa16(Kn + r * KROW + j * 16, Kg + (size_t)(kn + r) * 128 + j * 16);
                cpa16(Vn + r * KROW + j * 16, Vg + (size_t)r * 4096 + kn * 2 + j * 16);
            }
            CP_COMMIT();
        }

        // two 32-key half-passes
        #pragma unroll
        for (int kh = 0; kh < 2; kh++) {
            const int kc = k0 + 32 * kh + 2 * lt;   // global key pair base (am)
            const int kw = 32 * kh + 2 * lt;        // within-tile key word base (Dm)

            // S = Q K^T for keys [32kh, 32kh+32)
            float s[4][8];
            #pragma unroll
            for (int nt = 0; nt < 4; nt++)
                #pragma unroll
                for (int j = 0; j < 8; j++) s[nt][j] = 0.f;

            #pragma unroll
            for (int ks = 0; ks < 4; ks++) {
                #pragma unroll
                for (int nt = 0; nt < 4; nt++) {
                    uint2 kb = *(const uint2*)(Kc + (32 * kh + 8 * nt + lg) * KROW + ks * 32 + 8 * lt);
                    mma_f16(&s[nt][0], &qa[ks][0], (const unsigned*)&kb);
                    mma_f16(&s[nt][4], &qa[ks][4], (const unsigned*)&kb);
                }
            }

            // masks (am LDG / dm LDS) + fp32 exp + row sums; pack P a-frags
            unsigned pa[2][2][4];
            #pragma unroll
            for (int h2 = 0; h2 < 2; h2++) {
                const int ra = 32 * w + 16 * h2 + lg;
                #pragma unroll
                for (int nt = 0; nt < 4; nt++) {
                    const float2 amv = *(const float2*)&amb[kc + 8 * nt];
                    const float2 d0 = *(const float2*)(Dm + (ra    ) * DMROW + (kw + 8 * nt) * 4);
                    const float2 d1 = *(const float2*)(Dm + (ra + 8) * DMROW + (kw + 8 * nt) * 4);
                    const float p00 = ex2f(fmaf(d0.x, L2E, fmaf(amv.x, L2E, s[nt][4*h2+0])));
                    const float p01 = ex2f(fmaf(d0.y, L2E, fmaf(amv.y, L2E, s[nt][4*h2+1])));
                    const float p10 = ex2f(fmaf(d1.x, L2E, fmaf(amv.x, L2E, s[nt][4*h2+2])));
                    const float p11 = ex2f(fmaf(d1.y, L2E, fmaf(amv.y, L2E, s[nt][4*h2+3])));
                    lr[2*h2    ] += p00 + p01;
                    lr[2*h2 + 1] += p10 + p11;
                    pa[h2][nt >> 1][(nt & 1) * 2 + 0] = h2pk(p00, p01);
                    pa[h2][nt >> 1][(nt & 1) * 2 + 1] = h2pk(p10, p11);
                }
            }

            // O += P V for this key half
            #pragma unroll
            for (int ks2 = 0; ks2 < 2; ks2++) {
                const int kso = (2 * kh + ks2) * 32;
                #pragma unroll
                for (int nt = 0; nt < 8; nt++) {
                    uint2 vb = *(const uint2*)(Vc + (8 * nt + lg) * KROW + kso + 8 * lt);
                    mma_f16(&o[nt][0], pa[0][ks2], (const unsigned*)&vb);
                    mma_f16(&o[nt][4], pa[1][ks2], (const unsigned*)&vb);
                }
            }
        }

        // dm[t] fully consumed; stage dm[t+1]
        __syncthreads();
        if (t + 1 < NT) {
            const int kn = k0 + 64;
            #pragma unroll
            for (int i = 0; i < 16; i++) {
                const int c = tid + 128 * i;
                const int r = c >> 4, j = c & 15;
                cpa16(Dm + r * DMROW + j * 16, &dmb[(size_t)r * Sq + kn + 4 * j]);
            }
            CP_COMMIT();
        }
    }

    // row-sum reduce across the 4 lt lanes, normalize, write out
    #pragma unroll
    for (int i = 0; i < 4; i++) {
        lr[i] += __shfl_xor_sync(0xffffffffu, lr[i], 1);
        lr[i] += __shfl_xor_sync(0xffffffffu, lr[i], 2);
    }
    const float inv0 = 1.0f / lr[0];
    const float inv1 = 1.0f / lr[1];
    const float inv2 = 1.0f / lr[2];
    const float inv3 = 1.0f / lr[3];

    #pragma unroll
    for (int nt = 0; nt < 8; nt++) {
        const int col = h * HD + 8 * nt + 2 * lt;
        float2 r;
        r.x = o[nt][0] * inv0; r.y = o[nt][1] * inv0;
        *(float2*)&out[((size_t)b * Sq + qr     ) * Emb + col] = r;
        r.x = o[nt][2] * inv1; r.y = o[nt][3] * inv1;
        *(float2*)&out[((size_t)b * Sq + qr +  8) * Emb + col] = r;
        r.x = o[nt][4] * inv2; r.y = o[nt][5] * inv2;
        *(float2*)&out[((size_t)b * Sq + qr + 16) * Emb + col] = r;
        r.x = o[nt][6] * inv3; r.y = o[nt][7] * inv3;
        *(float2*)&out[((size_t)b * Sq + qr + 24) * Emb + col] = r;
    }
}

// ---------------------------------------------------------------------------
extern "C" void kernel_launch(void* const* d_in, const int* in_sizes, int n_in,
                              void* d_out, int out_size)
{
    const float* X  = (const float*)d_in[0];
    const float* am = (const float*)d_in[1];
    const float* dm = (const float*)d_in[2];
    const float* Wq = (const float*)d_in[3];
    const float* bq = (const float*)d_in[4];
    const float* Wk = (const float*)d_in[5];
    const float* bk = (const float*)d_in[6];
    const float* Wv = (const float*)d_in[7];
    const float* bv = (const float*)d_in[8];
    float* out = (float*)d_out;

    precvt_kernel<<<(CVT_TOT + 255) / 256, 256>>>(X, Wq, Wk, Wv);

    qkv_kernel<<<dim3(18, 64), 256>>>(bq, bk, bv);

    cudaFuncSetAttribute(attn_kernel,
                         cudaFuncAttributeMaxDynamicSharedMemorySize,
                         ATTN_SMEM);
    attn_kernel<<<dim3(Sq / 128, NH, Bsz), 128, ATTN_SMEM>>>(am, dm, out);
}